// round 2
// baseline (speedup 1.0000x reference)
#include <cuda_runtime.h>
#include <cstdint>

// Problem constants (fixed shapes per reference)
constexpr int Bc = 32;
constexpr int Hc = 512;
constexpr int Wc = 512;
constexpr int Pc = 100000;
constexpr long long Nc = (long long)Bc * Pc;   // 3,200,000 points
constexpr int BDIM = 256;
constexpr int PPT  = 4;                         // points per thread
constexpr int NBLK = (int)(Nc / ((long long)BDIM * PPT));  // 3125 blocks
static_assert(Nc % ((long long)BDIM * PPT) == 0, "grid must tile exactly");
static_assert(Pc % PPT == 0, "4 consecutive points always share a batch index");

__device__ float g_partial[NBLK];

__device__ __forceinline__ float point_loss(float zA, float zB, int o) {
    float d  = zA - zB;
    float gt = (float)o - 1.0f;          // in {-1, 0, +1}
    float sm = log1pf(expf(-gt * d));    // soft-margin branch (gt = +/-1)
    return (o == 1) ? (d * d) : sm;
}

__global__ __launch_bounds__(BDIM)
void loss_kernel(const float* __restrict__ img,
                 const int* __restrict__ xA,
                 const int* __restrict__ yA,
                 const int* __restrict__ xB,
                 const int* __restrict__ yB,
                 const int* __restrict__ ord)
{
    const long long base = ((long long)blockIdx.x * BDIM + threadIdx.x) * PPT;

    // 4 consecutive points: same batch (P % 4 == 0, base % 4 == 0)
    const int b = (int)(base / Pc);
    const float* __restrict__ imgb = img + (long long)b * (Hc * Wc);

    // 128-bit vector loads of all five int32 streams
    int4 xa = *reinterpret_cast<const int4*>(xA + base);
    int4 ya = *reinterpret_cast<const int4*>(yA + base);
    int4 xb = *reinterpret_cast<const int4*>(xB + base);
    int4 yb = *reinterpret_cast<const int4*>(yB + base);
    int4 o4 = *reinterpret_cast<const int4*>(ord + base);

    // Gather offsets: y*W + x  (W = 512 -> shift by 9)
    unsigned offA0 = ((unsigned)ya.x << 9) | (unsigned)xa.x;
    unsigned offA1 = ((unsigned)ya.y << 9) | (unsigned)xa.y;
    unsigned offA2 = ((unsigned)ya.z << 9) | (unsigned)xa.z;
    unsigned offA3 = ((unsigned)ya.w << 9) | (unsigned)xa.w;
    unsigned offB0 = ((unsigned)yb.x << 9) | (unsigned)xb.x;
    unsigned offB1 = ((unsigned)yb.y << 9) | (unsigned)xb.y;
    unsigned offB2 = ((unsigned)yb.z << 9) | (unsigned)xb.z;
    unsigned offB3 = ((unsigned)yb.w << 9) | (unsigned)xb.w;

    // Issue all 8 gathers before consuming (MLP)
    float zA0 = __ldg(imgb + offA0);
    float zA1 = __ldg(imgb + offA1);
    float zA2 = __ldg(imgb + offA2);
    float zA3 = __ldg(imgb + offA3);
    float zB0 = __ldg(imgb + offB0);
    float zB1 = __ldg(imgb + offB1);
    float zB2 = __ldg(imgb + offB2);
    float zB3 = __ldg(imgb + offB3);

    float s = point_loss(zA0, zB0, o4.x)
            + point_loss(zA1, zB1, o4.y)
            + point_loss(zA2, zB2, o4.z)
            + point_loss(zA3, zB3, o4.w);

    // Warp reduce
    #pragma unroll
    for (int off = 16; off > 0; off >>= 1)
        s += __shfl_xor_sync(0xFFFFFFFFu, s, off);

    // Block reduce via shared
    __shared__ float warp_sums[BDIM / 32];
    int lane = threadIdx.x & 31;
    int wid  = threadIdx.x >> 5;
    if (lane == 0) warp_sums[wid] = s;
    __syncthreads();
    if (wid == 0) {
        float v = (lane < BDIM / 32) ? warp_sums[lane] : 0.0f;
        #pragma unroll
        for (int off = 4; off > 0; off >>= 1)
            v += __shfl_xor_sync(0xFFFFFFFFu, v, off);
        if (lane == 0) g_partial[blockIdx.x] = v;
    }
}

__global__ __launch_bounds__(1024)
void reduce_kernel(float* __restrict__ out)
{
    float s = 0.0f;
    for (int i = threadIdx.x; i < NBLK; i += 1024)
        s += g_partial[i];

    #pragma unroll
    for (int off = 16; off > 0; off >>= 1)
        s += __shfl_xor_sync(0xFFFFFFFFu, s, off);

    __shared__ float warp_sums[32];
    int lane = threadIdx.x & 31;
    int wid  = threadIdx.x >> 5;
    if (lane == 0) warp_sums[wid] = s;
    __syncthreads();
    if (wid == 0) {
        float v = (lane < 32) ? warp_sums[lane] : 0.0f;
        #pragma unroll
        for (int off = 16; off > 0; off >>= 1)
            v += __shfl_xor_sync(0xFFFFFFFFu, v, off);
        if (lane == 0) out[0] = v * (1.0f / (float)Nc);
    }
}

extern "C" void kernel_launch(void* const* d_in, const int* in_sizes, int n_in,
                              void* d_out, int out_size)
{
    const float* img = (const float*)d_in[0];
    const int*   xA  = (const int*)d_in[1];
    const int*   yA  = (const int*)d_in[2];
    const int*   xB  = (const int*)d_in[3];
    const int*   yB  = (const int*)d_in[4];
    const int*   ord = (const int*)d_in[5];
    float* out = (float*)d_out;

    loss_kernel<<<NBLK, BDIM>>>(img, xA, yA, xB, yB, ord);
    reduce_kernel<<<1, 1024>>>(out);
}

// round 3
// speedup vs baseline: 1.0060x; 1.0060x over previous
#include <cuda_runtime.h>
#include <cstdint>

constexpr int Bc = 32;
constexpr int Hc = 512;
constexpr int Wc = 512;
constexpr int Pc = 100000;
constexpr long long Nc = (long long)Bc * Pc;   // 3,200,000 points
constexpr int BDIM = 128;
constexpr int PPT  = 8;                        // points per thread
constexpr int NBLK = (int)(Nc / ((long long)BDIM * PPT));  // 3125 blocks
static_assert(Nc % ((long long)BDIM * PPT) == 0, "grid must tile exactly");
static_assert(Pc % PPT == 0, "8 consecutive points always share a batch index");

__device__ float    g_partial[NBLK];
__device__ unsigned g_count = 0;   // returns to 0 at the end of every launch

__device__ __forceinline__ float point_loss(float zA, float zB, int o) {
    float d  = zA - zB;
    float gt = (float)o - 1.0f;          // in {-1, 0, +1}
    float sm = log1pf(expf(-gt * d));    // soft-margin branch (gt = +/-1)
    return (o == 1) ? (d * d) : sm;
}

__global__ __launch_bounds__(BDIM)
void loss_kernel(const float* __restrict__ img,
                 const int* __restrict__ xA,
                 const int* __restrict__ yA,
                 const int* __restrict__ xB,
                 const int* __restrict__ yB,
                 const int* __restrict__ ord,
                 float* __restrict__ out)
{
    const long long base = ((long long)blockIdx.x * BDIM + threadIdx.x) * PPT;

    // 8 consecutive points: same batch (P % 8 == 0, base % 8 == 0)
    const int b = (int)(base / Pc);
    const float* __restrict__ imgb = img + (long long)b * (Hc * Wc);

    // 128-bit vector loads of all five int32 streams (2x int4 each)
    int4 xa0 = *reinterpret_cast<const int4*>(xA + base);
    int4 xa1 = *reinterpret_cast<const int4*>(xA + base + 4);
    int4 ya0 = *reinterpret_cast<const int4*>(yA + base);
    int4 ya1 = *reinterpret_cast<const int4*>(yA + base + 4);
    int4 xb0 = *reinterpret_cast<const int4*>(xB + base);
    int4 xb1 = *reinterpret_cast<const int4*>(xB + base + 4);
    int4 yb0 = *reinterpret_cast<const int4*>(yB + base);
    int4 yb1 = *reinterpret_cast<const int4*>(yB + base + 4);
    int4 o0  = *reinterpret_cast<const int4*>(ord + base);
    int4 o1  = *reinterpret_cast<const int4*>(ord + base + 4);

    // Offsets: y*512 + x
    unsigned offA[PPT], offB[PPT];
    offA[0] = ((unsigned)ya0.x << 9) | (unsigned)xa0.x;
    offA[1] = ((unsigned)ya0.y << 9) | (unsigned)xa0.y;
    offA[2] = ((unsigned)ya0.z << 9) | (unsigned)xa0.z;
    offA[3] = ((unsigned)ya0.w << 9) | (unsigned)xa0.w;
    offA[4] = ((unsigned)ya1.x << 9) | (unsigned)xa1.x;
    offA[5] = ((unsigned)ya1.y << 9) | (unsigned)xa1.y;
    offA[6] = ((unsigned)ya1.z << 9) | (unsigned)xa1.z;
    offA[7] = ((unsigned)ya1.w << 9) | (unsigned)xa1.w;
    offB[0] = ((unsigned)yb0.x << 9) | (unsigned)xb0.x;
    offB[1] = ((unsigned)yb0.y << 9) | (unsigned)xb0.y;
    offB[2] = ((unsigned)yb0.z << 9) | (unsigned)xb0.z;
    offB[3] = ((unsigned)yb0.w << 9) | (unsigned)xb0.w;
    offB[4] = ((unsigned)yb1.x << 9) | (unsigned)xb1.x;
    offB[5] = ((unsigned)yb1.y << 9) | (unsigned)xb1.y;
    offB[6] = ((unsigned)yb1.z << 9) | (unsigned)xb1.z;
    offB[7] = ((unsigned)yb1.w << 9) | (unsigned)xb1.w;

    // Issue all 16 gathers before consuming (MLP)
    float zA[PPT], zB[PPT];
    #pragma unroll
    for (int i = 0; i < PPT; i++) zA[i] = __ldg(imgb + offA[i]);
    #pragma unroll
    for (int i = 0; i < PPT; i++) zB[i] = __ldg(imgb + offB[i]);

    int o[PPT] = {o0.x, o0.y, o0.z, o0.w, o1.x, o1.y, o1.z, o1.w};
    float s = 0.0f;
    #pragma unroll
    for (int i = 0; i < PPT; i++) s += point_loss(zA[i], zB[i], o[i]);

    // Warp reduce
    #pragma unroll
    for (int off = 16; off > 0; off >>= 1)
        s += __shfl_xor_sync(0xFFFFFFFFu, s, off);

    // Block reduce via shared
    __shared__ float warp_sums[BDIM / 32];
    int lane = threadIdx.x & 31;
    int wid  = threadIdx.x >> 5;
    if (lane == 0) warp_sums[wid] = s;
    __syncthreads();

    __shared__ bool is_last;
    if (threadIdx.x == 0) {
        float v = warp_sums[0];
        #pragma unroll
        for (int w = 1; w < BDIM / 32; w++) v += warp_sums[w];
        g_partial[blockIdx.x] = v;
        __threadfence();
        unsigned prev = atomicAdd(&g_count, 1u);
        is_last = (prev == (unsigned)(NBLK - 1));
    }
    __syncthreads();

    // Last arriving block performs the final (deterministic-order) reduction
    if (is_last) {
        float v = 0.0f;
        for (int i = threadIdx.x; i < NBLK; i += BDIM)
            v += g_partial[i];

        #pragma unroll
        for (int off = 16; off > 0; off >>= 1)
            v += __shfl_xor_sync(0xFFFFFFFFu, v, off);

        if (lane == 0) warp_sums[wid] = v;
        __syncthreads();
        if (threadIdx.x == 0) {
            float t = warp_sums[0];
            #pragma unroll
            for (int w = 1; w < BDIM / 32; w++) t += warp_sums[w];
            out[0] = t * (1.0f / (float)Nc);
            g_count = 0;           // reset for next graph replay
        }
    }
}

extern "C" void kernel_launch(void* const* d_in, const int* in_sizes, int n_in,
                              void* d_out, int out_size)
{
    const float* img = (const float*)d_in[0];
    const int*   xA  = (const int*)d_in[1];
    const int*   yA  = (const int*)d_in[2];
    const int*   xB  = (const int*)d_in[3];
    const int*   yB  = (const int*)d_in[4];
    const int*   ord = (const int*)d_in[5];
    float* out = (float*)d_out;

    loss_kernel<<<NBLK, BDIM>>>(img, xA, yA, xB, yB, ord, out);
}